// round 1
// baseline (speedup 1.0000x reference)
#include <cuda_runtime.h>

#define C_DIM 1024
#define TPB   128
#define XSTR  193   // per-thread smem slot: [0..63]=h, [64..127]=kc->mn, [128..191]=h1->res, +1 pad

__device__ float g_adj[2 * C_DIM];

__device__ __forceinline__ float4 ldg4(const float* p) {
    return __ldg(reinterpret_cast<const float4*>(p));
}
__device__ __forceinline__ float clipf(float v, float lo, float hi) {
    return fminf(fmaxf(v, lo), hi);
}
__device__ __forceinline__ float sigm(float x) { return 1.f / (1.f + expf(-x)); }

#define LOADB8(acc, p) do { float4 _b0 = ldg4(p), _b1 = ldg4((p) + 4);                       \
    acc[0]=_b0.x; acc[1]=_b0.y; acc[2]=_b0.z; acc[3]=_b0.w;                                  \
    acc[4]=_b1.x; acc[5]=_b1.y; acc[6]=_b1.z; acc[7]=_b1.w; } while (0)

#define FMA8(acc, xv, p) do { float4 _w0 = ldg4(p), _w1 = ldg4((p) + 4);                     \
    acc[0] += (xv)*_w0.x; acc[1] += (xv)*_w0.y; acc[2] += (xv)*_w0.z; acc[3] += (xv)*_w0.w;  \
    acc[4] += (xv)*_w1.x; acc[5] += (xv)*_w1.y; acc[6] += (xv)*_w1.z; acc[7] += (xv)*_w1.w; } while (0)

// 8-output chunk of a GEMV: acc[8] += in[0..L) @ W[L x 64][:, jc..jc+8)
template<bool CLIP5>
__device__ __forceinline__ void chunk8(const float* __restrict__ in, int L,
                                       const float* __restrict__ W, int jc, float acc[8]) {
#pragma unroll 4
    for (int i = 0; i < L; ++i) {
        float xi = in[i];
        if (CLIP5) xi = clipf(xi, -5.f, 5.f);
        FMA8(acc, xi, W + i * 64 + jc);
    }
}

// ---------------------------------------------------------------------------
// Kernel 1: adj[k][d] = clip( sum_c a0[c]*graphs[k][c][d] / max(sum(a0),1), -5, 5 )
// a0 = onehot[qt[0]] is 0/1 and very sparse -> deterministic compacted list.
// ---------------------------------------------------------------------------
__global__ void gkt_adj(const int* __restrict__ qt, const float* __restrict__ onehot,
                        const float* __restrict__ graphs) {
    __shared__ int nz[C_DIM];
    __shared__ int wcnt[32];
    __shared__ int woff[33];
    const int t = threadIdx.x;          // 1024 threads
    const int wid = t >> 5, lane = t & 31;

    const int q0 = qt[0];
    const float a = onehot[(long)q0 * C_DIM + t];
    const bool on = (a > 0.5f);
    unsigned bal = __ballot_sync(0xffffffffu, on);
    if (lane == 0) wcnt[wid] = __popc(bal);
    __syncthreads();
    if (t == 0) {
        int s = 0;
        for (int w = 0; w < 32; ++w) { woff[w] = s; s += wcnt[w]; }
        woff[32] = s;
    }
    __syncthreads();
    if (on) {
        int pos = woff[wid] + __popc(bal & ((1u << lane) - 1u));
        nz[pos] = t;
    }
    __syncthreads();
    const int n = woff[32];
    const float denom = fmaxf((float)n, 1.f);
#pragma unroll
    for (int k = 0; k < 2; ++k) {
        float s = 0.f;
        for (int idx = 0; idx < n; ++idx)
            s += graphs[k * C_DIM * C_DIM + nz[idx] * C_DIM + t];
        g_adj[k * C_DIM + t] = clipf(s / denom, -5.f, 5.f);
    }
}

// ---------------------------------------------------------------------------
// Kernel 2: fused per-row pipeline. One thread per (b, c) row.
// ---------------------------------------------------------------------------
__global__ __launch_bounds__(TPB) void gkt_main(
    const int*   __restrict__ qt,     const float* __restrict__ ht,
    const float* __restrict__ onehot, const float* __restrict__ kc,
    const float* __restrict__ nw_ptr,
    const float* __restrict__ Ws1, const float* __restrict__ bs1,
    const float* __restrict__ Ws2, const float* __restrict__ bs2,
    const float* __restrict__ Wn1, const float* __restrict__ bn1,
    const float* __restrict__ Wn2, const float* __restrict__ bn2,
    const float* __restrict__ ea_w,
    const float* __restrict__ We,  const float* __restrict__ be,
    const float* __restrict__ Wa,  const float* __restrict__ ba,
    const float* __restrict__ W_ih, const float* __restrict__ b_ih,
    const float* __restrict__ W_hh, const float* __restrict__ b_hh,
    const float* __restrict__ Wp,  const float* __restrict__ bp,
    float* __restrict__ out)
{
    extern __shared__ float smem[];
    const int tid  = threadIdx.x;
    const int row0 = blockIdx.x * TPB;
    const int b    = row0 >> 10;
    const int c0   = row0 & (C_DIM - 1);   // block never straddles a batch boundary (128 | 1024)

    // Cooperative, coalesced stage of x = [ht_row (64) | kc_row (64)] into padded slots.
    for (int i = tid; i < TPB * 64; i += TPB) {
        int r = i >> 6, col = i & 63;
        smem[r * XSTR + col]      = ht[(row0 + r) * 64 + col];
        smem[r * XSTR + 64 + col] = kc[(c0 + r) * 64 + col];
    }
    __syncthreads();

    float* xs = smem + tid * XSTR;
    const int   c = c0 + tid;
    const float m = __ldg(&onehot[(long)__ldg(&qt[b]) * C_DIM + c]);

    if (m > 0.5f) {
        // ---- self path: mn = clip(relu(relu(x@Ws1+bs1)@Ws2+bs2), -10, 10) ----
#pragma unroll
        for (int jc = 0; jc < 64; jc += 8) {
            float acc[8]; LOADB8(acc, bs1 + jc);
            chunk8<false>(xs, 128, Ws1, jc, acc);
#pragma unroll
            for (int u = 0; u < 8; ++u) xs[128 + jc + u] = fmaxf(acc[u], 0.f);
        }
#pragma unroll
        for (int jc = 0; jc < 64; jc += 8) {
            float acc[8]; LOADB8(acc, bs2 + jc);
            chunk8<false>(xs + 128, 64, Ws2, jc, acc);
#pragma unroll
            for (int u = 0; u < 8; ++u) xs[64 + jc + u] = clipf(fmaxf(acc[u], 0.f), -10.f, 10.f);
        }
    } else {
        // ---- neigh path: self_ht == 0, so only rows [128:256) of Wn1 matter,
        //      applied to clip(x, -5, 5). ----
        const float* Wn1k0 = Wn1 + 128 * 64;            // k=0, second-half rows
        const float* Wn1k1 = Wn1 + 256 * 64 + 128 * 64; // k=1, second-half rows

#pragma unroll
        for (int jc = 0; jc < 64; jc += 8) {
            float acc[8]; LOADB8(acc, bn1 + jc);
            chunk8<true>(xs, 128, Wn1k0, jc, acc);
#pragma unroll
            for (int u = 0; u < 8; ++u) xs[128 + jc + u] = fmaxf(acc[u], 0.f);
        }
        float nb0[64];
#pragma unroll
        for (int jc = 0; jc < 64; jc += 8) {
            float acc[8]; LOADB8(acc, bn2 + jc);
            chunk8<false>(xs + 128, 64, Wn2, jc, acc);
#pragma unroll
            for (int u = 0; u < 8; ++u) nb0[jc + u] = fminf(fmaxf(acc[u], 0.f), 5.f);
        }
#pragma unroll
        for (int jc = 0; jc < 64; jc += 8) {
            float acc[8]; LOADB8(acc, bn1 + 64 + jc);
            chunk8<true>(xs, 128, Wn1k1, jc, acc);
#pragma unroll
            for (int u = 0; u < 8; ++u) xs[128 + jc + u] = fmaxf(acc[u], 0.f);
        }
        const float aj0 = g_adj[c];
        const float aj1 = g_adj[C_DIM + c];
        const float w   = clipf(__ldg(nw_ptr), 0.1f, 0.9f);
#pragma unroll
        for (int jc = 0; jc < 64; jc += 8) {
            float acc[8]; LOADB8(acc, bn2 + 64 + jc);
            chunk8<false>(xs + 128, 64, Wn2 + 64 * 64, jc, acc);
#pragma unroll
            for (int u = 0; u < 8; ++u) {
                float nb1 = fminf(fmaxf(acc[u], 0.f), 5.f);
                float nf  = clipf(aj0 * nb0[jc + u], -5.f, 5.f);
                nf = clipf(w * nf + (1.f - w) * aj1 * nb1, -5.f, 5.f);
                xs[64 + jc + u] = nf;   // clip(+-50) is a no-op here
            }
        }
    }

    // ---- gating: res = mn - g*sigmoid(mn@We+be)*mn + g*tanh(mn@Wa+ba) ----
    const float g = __ldg(&ea_w[c]);
    const float* mn = xs + 64;
#pragma unroll
    for (int jc = 0; jc < 64; jc += 8) {
        float ae[8], aa[8];
        LOADB8(ae, be + jc); LOADB8(aa, ba + jc);
#pragma unroll 4
        for (int i = 0; i < 64; ++i) {
            float v = mn[i];
            FMA8(ae, v, We + i * 64 + jc);
            FMA8(aa, v, Wa + i * 64 + jc);
        }
#pragma unroll
        for (int u = 0; u < 8; ++u) {
            float mm = mn[jc + u];
            xs[128 + jc + u] = mm - g * sigm(ae[u]) * mm + g * tanhf(aa[u]);
        }
    }

    // ---- GRU + readout ----
    const float* resv = xs + 128;
    const float* hvec = xs;
    float y = __ldg(bp);
#pragma unroll
    for (int jc = 0; jc < 64; jc += 8) {
        float ir[8], iz[8], inn[8], hr[8], hz[8], hn[8];
        LOADB8(ir, b_ih + jc); LOADB8(iz, b_ih + 64 + jc); LOADB8(inn, b_ih + 128 + jc);
        LOADB8(hr, b_hh + jc); LOADB8(hz, b_hh + 64 + jc); LOADB8(hn, b_hh + 128 + jc);
#pragma unroll 2
        for (int i = 0; i < 64; ++i) {
            float rv = resv[i];
            float hh = hvec[i];
            const float* wi = W_ih + i * 192;
            const float* wh = W_hh + i * 192;
            FMA8(ir, rv, wi + jc); FMA8(iz, rv, wi + 64 + jc); FMA8(inn, rv, wi + 128 + jc);
            FMA8(hr, hh, wh + jc); FMA8(hz, hh, wh + 64 + jc); FMA8(hn,  hh, wh + 128 + jc);
        }
#pragma unroll
        for (int u = 0; u < 8; ++u) {
            float r  = sigm(ir[u] + hr[u]);
            float z  = sigm(iz[u] + hz[u]);
            float n  = tanhf(inn[u] + r * hn[u]);
            float hx = (1.f - z) * n + z * hvec[jc + u];
            y += hx * __ldg(Wp + jc + u);
        }
    }
    out[row0 + tid] = sigm(y);
}

extern "C" void kernel_launch(void* const* d_in, const int* in_sizes, int n_in,
                              void* d_out, int out_size) {
    // input order per metadata: xt, qt, ht, qt_kc_one_hot, kc_embeddings, graphs,
    // neigh_weight, Ws1, bs1, Ws2, bs2, Wn1, bn1, Wn2, bn2, ea_w, We, be, Wa, ba,
    // W_ih, b_ih, W_hh, b_hh, Wp, bp          (xt is unused by the reference)
    const int*   qt     = (const int*)  d_in[1];
    const float* ht     = (const float*)d_in[2];
    const float* onehot = (const float*)d_in[3];
    const float* kc     = (const float*)d_in[4];
    const float* graphs = (const float*)d_in[5];
    const float* nw     = (const float*)d_in[6];
    const float* Ws1    = (const float*)d_in[7];
    const float* bs1    = (const float*)d_in[8];
    const float* Ws2    = (const float*)d_in[9];
    const float* bs2    = (const float*)d_in[10];
    const float* Wn1    = (const float*)d_in[11];
    const float* bn1    = (const float*)d_in[12];
    const float* Wn2    = (const float*)d_in[13];
    const float* bn2    = (const float*)d_in[14];
    const float* ea_w   = (const float*)d_in[15];
    const float* We     = (const float*)d_in[16];
    const float* be     = (const float*)d_in[17];
    const float* Wa     = (const float*)d_in[18];
    const float* ba     = (const float*)d_in[19];
    const float* W_ih   = (const float*)d_in[20];
    const float* b_ih   = (const float*)d_in[21];
    const float* W_hh   = (const float*)d_in[22];
    const float* b_hh   = (const float*)d_in[23];
    const float* Wp     = (const float*)d_in[24];
    const float* bp     = (const float*)d_in[25];
    float* out = (float*)d_out;

    gkt_adj<<<1, 1024>>>(qt, onehot, graphs);

    const int smem_bytes = TPB * XSTR * (int)sizeof(float);   // 98816 B
    cudaFuncSetAttribute(gkt_main, cudaFuncAttributeMaxDynamicSharedMemorySize, smem_bytes);
    const int nrows = 256 * C_DIM;
    gkt_main<<<nrows / TPB, TPB, smem_bytes>>>(
        qt, ht, onehot, kc, nw,
        Ws1, bs1, Ws2, bs2, Wn1, bn1, Wn2, bn2,
        ea_w, We, be, Wa, ba, W_ih, b_ih, W_hh, b_hh, Wp, bp,
        out);
}

// round 2
// speedup vs baseline: 2.7676x; 2.7676x over previous
#include <cuda_runtime.h>

typedef unsigned long long ull;

#define C_DIM 1024
#define TPB   256
#define TILE_R 128
#define PAD  130           // row stride for transposed activation buffers

// smem arena layout (floats)
#define SM_XT 0                         // [128][130] x clipped(+-5), transposed: XT[k][row]
#define SM_XH (128*PAD)                 // [64][130]  raw ht, transposed
#define SM_WD (SM_XH + 64*PAD)          // [64][128]  duplicated weight tile (w,w) pairs
#define SM_B1 (SM_WD + 64*128)          // [64][130]
#define SM_B2 (SM_B1 + 64*PAD)
#define SM_B3 (SM_B2 + 64*PAD)
#define SM_TOT (SM_B3 + 64*PAD)         // 58112 floats = 232448 B (== 227KB opt-in max)

__device__ float g_adj[2 * C_DIM];

__device__ __forceinline__ float clipf(float v, float lo, float hi) {
    return fminf(fmaxf(v, lo), hi);
}
__device__ __forceinline__ float sigm(float x) { return 1.f / (1.f + expf(-x)); }

__device__ __forceinline__ void ffma2(ull& d, ull a, ull b) {
    asm("fma.rn.f32x2 %0, %1, %2, %0;" : "+l"(d) : "l"(a), "l"(b));
}
__device__ __forceinline__ ull pk(float x, float y) {
    ull v; asm("mov.b64 %0, {%1, %2};" : "=l"(v) : "f"(x), "f"(y)); return v;
}
__device__ __forceinline__ float2 upk(ull v) {
    float2 r; asm("mov.b64 {%0, %1}, %2;" : "=f"(r.x), "=f"(r.y) : "l"(v)); return r;
}

// ---------------------------------------------------------------------------
// adj pre-kernel (unchanged from R1; ~3us)
// ---------------------------------------------------------------------------
__global__ void gkt_adj(const int* __restrict__ qt, const float* __restrict__ onehot,
                        const float* __restrict__ graphs) {
    __shared__ int nz[C_DIM];
    __shared__ int wcnt[32];
    __shared__ int woff[33];
    const int t = threadIdx.x, wid = t >> 5, lane = t & 31;
    const int q0 = qt[0];
    const bool on = (onehot[(long)q0 * C_DIM + t] > 0.5f);
    unsigned bal = __ballot_sync(0xffffffffu, on);
    if (lane == 0) wcnt[wid] = __popc(bal);
    __syncthreads();
    if (t == 0) { int s = 0; for (int w = 0; w < 32; ++w) { woff[w] = s; s += wcnt[w]; } woff[32] = s; }
    __syncthreads();
    if (on) nz[woff[wid] + __popc(bal & ((1u << lane) - 1u))] = t;
    __syncthreads();
    const int n = woff[32];
    const float denom = fmaxf((float)n, 1.f);
#pragma unroll
    for (int k = 0; k < 2; ++k) {
        float s = 0.f;
        for (int idx = 0; idx < n; ++idx)
            s += graphs[k * C_DIM * C_DIM + nz[idx] * C_DIM + t];
        g_adj[k * C_DIM + t] = clipf(s / denom, -5.f, 5.f);
    }
}

// ---------------------------------------------------------------------------
// helpers for the fused GEMM chain
// ---------------------------------------------------------------------------

// Stage a 64x64 weight tile into WD with (w,w) duplication for f32x2 b-operands.
__device__ __forceinline__ void stage_w(float* __restrict__ WD, const float* __restrict__ src,
                                        int rstride, int t) {
#pragma unroll
    for (int i = t; i < 64 * 64; i += TPB) {
        int kk = i >> 6, o = i & 63;
        float w = __ldg(src + kk * rstride + o);
        *reinterpret_cast<float2*>(WD + kk * 128 + 2 * o) = make_float2(w, w);
    }
}

// acc[u][p] += A[kk][rows] * W[kk][o]:  thread = 4 rows (2 f32x2 pairs) x 8 outs (o = tx+8u)
__device__ __forceinline__ void gemm_acc(const float* __restrict__ A, const float* __restrict__ WD,
                                         int ty, int tx, ull acc[8][2]) {
    const float* Ab = A + ty * 4;
    const float* Wb = WD + 2 * tx;
#pragma unroll 4
    for (int kk = 0; kk < 64; ++kk) {
        ull a0 = *reinterpret_cast<const ull*>(Ab + kk * PAD);
        ull a1 = *reinterpret_cast<const ull*>(Ab + kk * PAD + 2);
        const float* wk = Wb + kk * 128;
#pragma unroll
        for (int u = 0; u < 8; ++u) {
            ull b = *reinterpret_cast<const ull*>(wk + 16 * u);
            ffma2(acc[u][0], a0, b);
            ffma2(acc[u][1], a1, b);
        }
    }
}

__device__ __forceinline__ void init_bias(ull acc[8][2], const float* __restrict__ b1p,
                                          const float* __restrict__ b2p, int tx) {
#pragma unroll
    for (int u = 0; u < 8; ++u) {
        int o = tx + 8 * u;
        float v = __ldg(b1p + o);
        if (b2p) v += __ldg(b2p + o);
        ull pv = pk(v, v);
        acc[u][0] = pv; acc[u][1] = pv;
    }
}

// ---------------------------------------------------------------------------
// fused main kernel: 128 rows/block, 256 threads, packed-f32x2 GEMM chain
// ---------------------------------------------------------------------------
__global__ __launch_bounds__(TPB, 1) void gkt_main(
    const int*   __restrict__ qt,     const float* __restrict__ ht,
    const float* __restrict__ onehot, const float* __restrict__ kc,
    const float* __restrict__ nw_ptr,
    const float* __restrict__ Ws1, const float* __restrict__ bs1,
    const float* __restrict__ Ws2, const float* __restrict__ bs2,
    const float* __restrict__ Wn1, const float* __restrict__ bn1,
    const float* __restrict__ Wn2, const float* __restrict__ bn2,
    const float* __restrict__ ea_w,
    const float* __restrict__ We,  const float* __restrict__ be,
    const float* __restrict__ Wa,  const float* __restrict__ ba,
    const float* __restrict__ W_ih, const float* __restrict__ b_ih,
    const float* __restrict__ W_hh, const float* __restrict__ b_hh,
    const float* __restrict__ Wp,  const float* __restrict__ bp,
    float* __restrict__ out)
{
    extern __shared__ float sm[];
    float* XT = sm + SM_XT;
    float* XH = sm + SM_XH;
    float* WD = sm + SM_WD;
    float* B1 = sm + SM_B1;
    float* B2 = sm + SM_B2;
    float* B3 = sm + SM_B3;
    float* B4 = XT;                 // XT region reused after self fix-up
    float* tmp = WD;                // fix-up scratch (floats 0..63 of WD)
    int*   mlist = (int*)(WD + 64); // fix-up row list (ints 64..191)
    int*   mcnt  = (int*)(WD + 192);

    const int t  = threadIdx.x;
    const int tx = t & 7, ty = t >> 3;        // outs o = tx+8u, rows = ty*4 .. ty*4+3
    const int row0 = blockIdx.x * TILE_R;
    const int b  = row0 >> 10;
    const int c0 = row0 & (C_DIM - 1);
    const int q  = __ldg(&qt[b]);

    // ---- stage X transposed: XT clipped(+-5), XH raw ht ----
#pragma unroll
    for (int i = t; i < TILE_R * 64; i += TPB) {
        int row = i >> 6, k = i & 63;
        float hv = ht[(row0 + row) * 64 + k];
        XH[k * PAD + row] = hv;
        XT[k * PAD + row] = clipf(hv, -5.f, 5.f);
        XT[(64 + k) * PAD + row] = clipf(kc[(c0 + row) * 64 + k], -5.f, 5.f);
    }

    ull acc[8][2];
    const float wcl = clipf(__ldg(nw_ptr), 0.1f, 0.9f);

    // ================= stage 1: H1(k=0) = relu(X @ Wn1[0][128:256]) ========
    init_bias(acc, bn1, nullptr, tx);
    __syncthreads();
    stage_w(WD, Wn1 + (0 * 256 + 128) * 64, 64, t);
    __syncthreads();
    gemm_acc(XT, WD, ty, tx, acc);
    __syncthreads();
    stage_w(WD, Wn1 + (0 * 256 + 192) * 64, 64, t);
    __syncthreads();
    gemm_acc(XT + 64 * PAD, WD, ty, tx, acc);
#pragma unroll
    for (int u = 0; u < 8; ++u) {
        int o = tx + 8 * u;
#pragma unroll
        for (int p = 0; p < 2; ++p) {
            float2 v = upk(acc[u][p]);
            *reinterpret_cast<float2*>(B1 + o * PAD + ty * 4 + 2 * p) =
                make_float2(fmaxf(v.x, 0.f), fmaxf(v.y, 0.f));
        }
    }

    // ================= stage 2: nf0 = clip5(aj0 * clip5(relu(H1 @ Wn2[0]))) =
    init_bias(acc, bn2, nullptr, tx);
    __syncthreads();
    stage_w(WD, Wn2, 64, t);
    __syncthreads();
    gemm_acc(B1, WD, ty, tx, acc);
#pragma unroll
    for (int u = 0; u < 8; ++u) {
        int o = tx + 8 * u;
#pragma unroll
        for (int p = 0; p < 2; ++p) {
            float2 v = upk(acc[u][p]);
            int r = ty * 4 + 2 * p;
            float a0 = __ldg(&g_adj[c0 + r]), a1 = __ldg(&g_adj[c0 + r + 1]);
            float nb0x = fminf(fmaxf(v.x, 0.f), 5.f);
            float nb0y = fminf(fmaxf(v.y, 0.f), 5.f);
            *reinterpret_cast<float2*>(B2 + o * PAD + r) =
                make_float2(clipf(a0 * nb0x, -5.f, 5.f), clipf(a1 * nb0y, -5.f, 5.f));
        }
    }

    // ================= stage 3: H1(k=1) ====================================
    init_bias(acc, bn1 + 64, nullptr, tx);
    __syncthreads();
    stage_w(WD, Wn1 + (1 * 256 + 128) * 64, 64, t);
    __syncthreads();
    gemm_acc(XT, WD, ty, tx, acc);
    __syncthreads();
    stage_w(WD, Wn1 + (1 * 256 + 192) * 64, 64, t);
    __syncthreads();
    gemm_acc(XT + 64 * PAD, WD, ty, tx, acc);
#pragma unroll
    for (int u = 0; u < 8; ++u) {
        int o = tx + 8 * u;
#pragma unroll
        for (int p = 0; p < 2; ++p) {
            float2 v = upk(acc[u][p]);
            *reinterpret_cast<float2*>(B1 + o * PAD + ty * 4 + 2 * p) =
                make_float2(fmaxf(v.x, 0.f), fmaxf(v.y, 0.f));
        }
    }

    // ================= stage 4: nf = clip5(w*nf0 + (1-w)*aj1*nb1) ==========
    init_bias(acc, bn2 + 64, nullptr, tx);
    __syncthreads();
    stage_w(WD, Wn2 + 64 * 64, 64, t);
    __syncthreads();
    gemm_acc(B1, WD, ty, tx, acc);
#pragma unroll
    for (int u = 0; u < 8; ++u) {
        int o = tx + 8 * u;
#pragma unroll
        for (int p = 0; p < 2; ++p) {
            float2 v = upk(acc[u][p]);
            int r = ty * 4 + 2 * p;
            float a1x = __ldg(&g_adj[C_DIM + c0 + r]), a1y = __ldg(&g_adj[C_DIM + c0 + r + 1]);
            float2 nf0 = *reinterpret_cast<float2*>(B2 + o * PAD + r);
            float nb1x = fminf(fmaxf(v.x, 0.f), 5.f);
            float nb1y = fminf(fmaxf(v.y, 0.f), 5.f);
            float nfx = clipf(wcl * nf0.x + (1.f - wcl) * a1x * nb1x, -5.f, 5.f);
            float nfy = clipf(wcl * nf0.y + (1.f - wcl) * a1y * nb1y, -5.f, 5.f);
            *reinterpret_cast<float2*>(B2 + o * PAD + r) = make_float2(nfx, nfy);
        }
    }

    // ================= stage 5: masked-row self-MLP fix-up (~0.5% of rows) ==
    __syncthreads();
    if (t == 0) *mcnt = 0;
    __syncthreads();
    if (t < TILE_R) {
        float m = __ldg(&onehot[(long)q * C_DIM + c0 + t]);
        if (m > 0.5f) { int pos = atomicAdd(mcnt, 1); mlist[pos] = t; }
    }
    __syncthreads();
    const int nm = *mcnt;
    for (int idx = 0; idx < nm; ++idx) {
        int row = mlist[idx];
        if (t < 64) {
            float a = __ldg(bs1 + t);
            for (int k = 0; k < 64; ++k)   a += XH[k * PAD + row] * __ldg(Ws1 + k * 64 + t);
            for (int k = 64; k < 128; ++k) a += XT[k * PAD + row] * __ldg(Ws1 + k * 64 + t);
            tmp[t] = fmaxf(a, 0.f);
        }
        __syncthreads();
        if (t < 64) {
            float a = __ldg(bs2 + t);
            for (int k = 0; k < 64; ++k) a += tmp[k] * __ldg(Ws2 + k * 64 + t);
            B2[t * PAD + row] = clipf(fmaxf(a, 0.f), -10.f, 10.f);
        }
        __syncthreads();
    }
    // B2 now holds m_next (mn)

    // ================= stage 6: sigE = sigmoid(mn @ We + be) -> B1 =========
    init_bias(acc, be, nullptr, tx);
    __syncthreads();
    stage_w(WD, We, 64, t);
    __syncthreads();
    gemm_acc(B2, WD, ty, tx, acc);
#pragma unroll
    for (int u = 0; u < 8; ++u) {
        int o = tx + 8 * u;
#pragma unroll
        for (int p = 0; p < 2; ++p) {
            float2 v = upk(acc[u][p]);
            *reinterpret_cast<float2*>(B1 + o * PAD + ty * 4 + 2 * p) =
                make_float2(sigm(v.x), sigm(v.y));
        }
    }

    // ================= stage 7: res = mn - g*sigE*mn + g*tanh(mn@Wa+ba) -> B3
    init_bias(acc, ba, nullptr, tx);
    __syncthreads();
    stage_w(WD, Wa, 64, t);
    __syncthreads();
    gemm_acc(B2, WD, ty, tx, acc);
#pragma unroll
    for (int u = 0; u < 8; ++u) {
        int o = tx + 8 * u;
#pragma unroll
        for (int p = 0; p < 2; ++p) {
            float2 v = upk(acc[u][p]);
            int r = ty * 4 + 2 * p;
            float gx = __ldg(&ea_w[c0 + r]), gy = __ldg(&ea_w[c0 + r + 1]);
            float2 mn = *reinterpret_cast<float2*>(B2 + o * PAD + r);
            float2 sg = *reinterpret_cast<float2*>(B1 + o * PAD + r);
            float rx = mn.x - gx * sg.x * mn.x + gx * tanhf(v.x);
            float ry = mn.y - gy * sg.y * mn.y + gy * tanhf(v.y);
            *reinterpret_cast<float2*>(B3 + o * PAD + r) = make_float2(rx, ry);
        }
    }

    // ================= stage 8: r = sigm(res@Wihr + ht@Whhr + b) -> B1 =====
    init_bias(acc, b_ih, b_hh, tx);
    __syncthreads();
    stage_w(WD, W_ih, 192, t);
    __syncthreads();
    gemm_acc(B3, WD, ty, tx, acc);
    __syncthreads();
    stage_w(WD, W_hh, 192, t);
    __syncthreads();
    gemm_acc(XH, WD, ty, tx, acc);
#pragma unroll
    for (int u = 0; u < 8; ++u) {
        int o = tx + 8 * u;
#pragma unroll
        for (int p = 0; p < 2; ++p) {
            float2 v = upk(acc[u][p]);
            *reinterpret_cast<float2*>(B1 + o * PAD + ty * 4 + 2 * p) =
                make_float2(sigm(v.x), sigm(v.y));
        }
    }

    // ================= stage 9: z -> B2 (mn dead) ==========================
    init_bias(acc, b_ih + 64, b_hh + 64, tx);
    __syncthreads();
    stage_w(WD, W_ih + 64, 192, t);
    __syncthreads();
    gemm_acc(B3, WD, ty, tx, acc);
    __syncthreads();
    stage_w(WD, W_hh + 64, 192, t);
    __syncthreads();
    gemm_acc(XH, WD, ty, tx, acc);
#pragma unroll
    for (int u = 0; u < 8; ++u) {
        int o = tx + 8 * u;
#pragma unroll
        for (int p = 0; p < 2; ++p) {
            float2 v = upk(acc[u][p]);
            *reinterpret_cast<float2*>(B2 + o * PAD + ty * 4 + 2 * p) =
                make_float2(sigm(v.x), sigm(v.y));
        }
    }

    // ================= stage 10a: hn = ht@Whhn + bhhn -> B4 (XT reuse) =====
    init_bias(acc, b_hh + 128, nullptr, tx);
    __syncthreads();
    stage_w(WD, W_hh + 128, 192, t);
    __syncthreads();
    gemm_acc(XH, WD, ty, tx, acc);
#pragma unroll
    for (int u = 0; u < 8; ++u) {
        int o = tx + 8 * u;
#pragma unroll
        for (int p = 0; p < 2; ++p) {
            float2 v = upk(acc[u][p]);
            *reinterpret_cast<float2*>(B4 + o * PAD + ty * 4 + 2 * p) = make_float2(v.x, v.y);
        }
    }

    // ================= stage 10b: n, h_next -> B1 ==========================
    init_bias(acc, b_ih + 128, nullptr, tx);
    __syncthreads();
    stage_w(WD, W_ih + 128, 192, t);
    __syncthreads();
    gemm_acc(B3, WD, ty, tx, acc);
#pragma unroll
    for (int u = 0; u < 8; ++u) {
        int o = tx + 8 * u;
#pragma unroll
        for (int p = 0; p < 2; ++p) {
            float2 v = upk(acc[u][p]);
            int r = ty * 4 + 2 * p;
            float2 hn = *reinterpret_cast<float2*>(B4 + o * PAD + r);
            float2 rr = *reinterpret_cast<float2*>(B1 + o * PAD + r);
            float2 zz = *reinterpret_cast<float2*>(B2 + o * PAD + r);
            float2 hv = *reinterpret_cast<float2*>(XH + o * PAD + r);
            float nx = tanhf(v.x + rr.x * hn.x);
            float ny = tanhf(v.y + rr.y * hn.y);
            float hx = (1.f - zz.x) * nx + zz.x * hv.x;
            float hy = (1.f - zz.y) * ny + zz.y * hv.y;
            *reinterpret_cast<float2*>(B1 + o * PAD + r) = make_float2(hx, hy);
        }
    }

    // ================= stage 11: y = sigm(h_next @ Wp + bp) ================
    __syncthreads();
    {
        int row = t >> 1, half = t & 1;
        float s = 0.f;
        const float* hb = B1 + half * 32 * PAD + row;
#pragma unroll
        for (int o = 0; o < 32; ++o)
            s += hb[o * PAD] * __ldg(Wp + half * 32 + o);
        s += __shfl_xor_sync(0xffffffffu, s, 1);
        if (half == 0)
            out[row0 + row] = sigm(s + __ldg(bp));
    }
}

extern "C" void kernel_launch(void* const* d_in, const int* in_sizes, int n_in,
                              void* d_out, int out_size) {
    const int*   qt     = (const int*)  d_in[1];
    const float* ht     = (const float*)d_in[2];
    const float* onehot = (const float*)d_in[3];
    const float* kc     = (const float*)d_in[4];
    const float* graphs = (const float*)d_in[5];
    const float* nw     = (const float*)d_in[6];
    const float* Ws1    = (const float*)d_in[7];
    const float* bs1    = (const float*)d_in[8];
    const float* Ws2    = (const float*)d_in[9];
    const float* bs2    = (const float*)d_in[10];
    const float* Wn1    = (const float*)d_in[11];
    const float* bn1    = (const float*)d_in[12];
    const float* Wn2    = (const float*)d_in[13];
    const float* bn2    = (const float*)d_in[14];
    const float* ea_w   = (const float*)d_in[15];
    const float* We     = (const float*)d_in[16];
    const float* be     = (const float*)d_in[17];
    const float* Wa     = (const float*)d_in[18];
    const float* ba     = (const float*)d_in[19];
    const float* W_ih   = (const float*)d_in[20];
    const float* b_ih   = (const float*)d_in[21];
    const float* W_hh   = (const float*)d_in[22];
    const float* b_hh   = (const float*)d_in[23];
    const float* Wp     = (const float*)d_in[24];
    const float* bp     = (const float*)d_in[25];
    float* out = (float*)d_out;

    gkt_adj<<<1, 1024>>>(qt, onehot, graphs);

    const int smem_bytes = SM_TOT * (int)sizeof(float);   // 232448 B
    cudaFuncSetAttribute(gkt_main, cudaFuncAttributeMaxDynamicSharedMemorySize, smem_bytes);
    const int nrows = 256 * C_DIM;
    gkt_main<<<nrows / TILE_R, TPB, smem_bytes>>>(
        qt, ht, onehot, kc, nw,
        Ws1, bs1, Ws2, bs2, Wn1, bn1, Wn2, bn2,
        ea_w, We, be, Wa, ba, W_ih, b_ih, W_hh, b_hh, Wp, bp,
        out);
}